// round 8
// baseline (speedup 1.0000x reference)
#include <cuda_runtime.h>

// Row-normalize: out[b,i,j] = adj[b,i,j] / sum_j adj[b,i,j]  (nan/inf inv -> 0)
// Two tensors of [16, 1024, 1024] fp32; output = concat(out0, out1).
//
// One warp owns TWO rows: row r of adj0 and row r of adj1 (same local index).
// All 16 float4 loads front-batched so the row-0 store burst is fully
// overlapped by row-1's in-flight loads (keeps DRAM read queue non-empty
// through write phases). Shuffle-only reduction, no smem, no barriers.

constexpr int N       = 1024;            // row length
constexpr int THREADS = 256;             // 8 warps/CTA
constexpr int WARPS   = THREADS / 32;
constexpr int VPT     = 8;               // float4 per thread per row

__global__ __launch_bounds__(THREADS)
void row_norm_kernel(const float* __restrict__ in0,
                     const float* __restrict__ in1,
                     float* __restrict__ out,
                     int rows_per_tensor)   // 16384
{
    const int lane = threadIdx.x & 31;
    const int wid  = threadIdx.x >> 5;

    const long long r = (long long)blockIdx.x * WARPS + wid;   // 0..16383

    const float4* __restrict__ s0 =
        reinterpret_cast<const float4*>(in0) + r * (N / 4) + lane;
    const float4* __restrict__ s1 =
        reinterpret_cast<const float4*>(in1) + r * (N / 4) + lane;
    float4* __restrict__ d0 =
        reinterpret_cast<float4*>(out) + r * (N / 4) + lane;
    float4* __restrict__ d1 =
        reinterpret_cast<float4*>(out) + (r + (long long)rows_per_tensor) * (N / 4) + lane;

    // Front-batch ALL 16 independent 128B loads (both rows).
    float4 a[VPT], b[VPT];
    #pragma unroll
    for (int i = 0; i < VPT; ++i) a[i] = __ldcs(s0 + i * 32);
    #pragma unroll
    for (int i = 0; i < VPT; ++i) b[i] = __ldcs(s1 + i * 32);

    // ---- Row 0 (adj0): waits only on a[], b[] still in flight ----
    float pa = 0.0f;
    #pragma unroll
    for (int i = 0; i < VPT; ++i)
        pa += ((a[i].x + a[i].y) + (a[i].z + a[i].w));
    #pragma unroll
    for (int off = 16; off > 0; off >>= 1)
        pa += __shfl_xor_sync(0xFFFFFFFFu, pa, off);

    float inva = 1.0f / pa;
    if (!isfinite(inva)) inva = 0.0f;

    #pragma unroll
    for (int i = 0; i < VPT; ++i) {
        a[i].x *= inva; a[i].y *= inva; a[i].z *= inva; a[i].w *= inva;
        __stcs(d0 + i * 32, a[i]);
    }

    // ---- Row 1 (adj1) ----
    float pb = 0.0f;
    #pragma unroll
    for (int i = 0; i < VPT; ++i)
        pb += ((b[i].x + b[i].y) + (b[i].z + b[i].w));
    #pragma unroll
    for (int off = 16; off > 0; off >>= 1)
        pb += __shfl_xor_sync(0xFFFFFFFFu, pb, off);

    float invb = 1.0f / pb;
    if (!isfinite(invb)) invb = 0.0f;

    #pragma unroll
    for (int i = 0; i < VPT; ++i) {
        b[i].x *= invb; b[i].y *= invb; b[i].z *= invb; b[i].w *= invb;
        __stcs(d1 + i * 32, b[i]);
    }
}

extern "C" void kernel_launch(void* const* d_in, const int* in_sizes, int n_in,
                              void* d_out, int out_size)
{
    const float* adj0 = (const float*)d_in[0];
    const float* adj1 = (const float*)d_in[1];
    float* out = (float*)d_out;

    const int rows_per_tensor = in_sizes[0] / N;          // 16384
    const int grid = rows_per_tensor / WARPS;             // 2048 CTAs

    row_norm_kernel<<<grid, THREADS>>>(adj0, adj1, out, rows_per_tensor);
}